// round 2
// baseline (speedup 1.0000x reference)
#include <cuda_runtime.h>
#include <math.h>

// ---------------- scratch (static __device__, no allocation) ----------------
static __device__ float2 g_F1[16 * 256 * 512];   // row-FFT of padded batch (rows 256..511 are zero, not stored)
static __device__ float  g_G [16 * 512 * 512];   // |F| stored transposed: G_T[b][l][k]
static __device__ float2 g_A [16 * 512 * 512];   // A_T[b][l][h] = ifft over k
static __device__ float  g_Pb[16 * 512 * 512];   // pseudo[b][h][w] (unscaled)
static __device__ float  g_Ph[16 * 512 * 512];   // pseudo transposed [h][w][b], scaled by 1/(H*W)
static __device__ float  g_part[45 * 16 * 64];   // contraction partials [tgroup][split][q*16+b]

#define PI_F 3.14159265358979f

// ---------------- 512-pt radix-2 DIT FFT, 4 lines per 256-thread block ------
__device__ __forceinline__ void fft512x4(float2 (*s)[512], int tid, float sgn) {
    // bit-reversal permutation (input already loaded in natural order)
#pragma unroll
    for (int k = 0; k < 8; ++k) {
        int idx = tid + 256 * k;
        int line = idx >> 9, i = idx & 511;
        int r = (int)(__brev((unsigned)i) >> 23);
        if (i < r) { float2 a = s[line][i]; s[line][i] = s[line][r]; s[line][r] = a; }
    }
    __syncthreads();
#pragma unroll
    for (int st = 1; st <= 9; ++st) {
        const int len = 1 << st, half = len >> 1;
        const float angf = sgn * (6.28318530717958647692f / (float)len);
#pragma unroll
        for (int k = 0; k < 4; ++k) {
            int idx = tid + 256 * k;
            int line = idx >> 8, bf = idx & 255;
            int j = bf & (half - 1);
            int pos = ((bf >> (st - 1)) << st) + j;
            float sw, cw;
            __sincosf(angf * (float)j, &sw, &cw);
            float2 u = s[line][pos];
            float2 v = s[line][pos + half];
            float wx = v.x * cw - v.y * sw;
            float wy = v.x * sw + v.y * cw;
            s[line][pos]        = make_float2(u.x + wx, u.y + wy);
            s[line][pos + half] = make_float2(u.x - wx, u.y - wy);
        }
        __syncthreads();
    }
}

// ---- pass 1: forward FFT along w of zero-padded rows (only h<256 nonzero) --
__global__ __launch_bounds__(256) void k_fft_rows_fwd(const float* __restrict__ x) {
    __shared__ float2 s[4][512];
    int bid = blockIdx.x;
    int b = bid >> 6, h0 = (bid & 63) << 2;
    int tid = threadIdx.x;
#pragma unroll
    for (int k = 0; k < 8; ++k) {
        int idx = tid + 256 * k, line = idx >> 9, i = idx & 511;
        float v = (i < 256) ? x[(size_t)(b * 256 + h0 + line) * 256 + i] : 0.f;
        s[line][i] = make_float2(v, 0.f);
    }
    __syncthreads();
    fft512x4(s, tid, -1.f);
#pragma unroll
    for (int k = 0; k < 8; ++k) {
        int idx = tid + 256 * k, line = idx >> 9, i = idx & 511;
        g_F1[(size_t)(b * 256 + h0 + line) * 512 + i] = s[line][i];
    }
}

// ---- pass 2: forward FFT along h (upper half zeros), then |F|, write G_T ---
__global__ __launch_bounds__(256) void k_fft_cols_fwd_abs() {
    __shared__ float2 s[4][512];
    int bid = blockIdx.x;
    int b = bid >> 7, l0 = (bid & 127) << 2;
    int tid = threadIdx.x;
#pragma unroll
    for (int k = 0; k < 8; ++k) {
        int idx = tid + 256 * k;
        int line = idx & 3, i = idx >> 2;
        float2 v = (i < 256) ? g_F1[(size_t)(b * 256 + i) * 512 + l0 + line]
                             : make_float2(0.f, 0.f);
        s[line][i] = v;
    }
    __syncthreads();
    fft512x4(s, tid, -1.f);
#pragma unroll
    for (int k = 0; k < 8; ++k) {
        int idx = tid + 256 * k, line = idx >> 9, kk = idx & 511;
        float2 f = s[line][kk];
        g_G[(size_t)(b * 512 + l0 + line) * 512 + kk] = sqrtf(f.x * f.x + f.y * f.y);
    }
}

// ---- pass 3: inverse FFT along k of G_T rows -> A_T[b][l][h] ---------------
__global__ __launch_bounds__(256) void k_fft_rows_inv() {
    __shared__ float2 s[4][512];
    int bid = blockIdx.x;
    int b = bid >> 7, l0 = (bid & 127) << 2;
    int tid = threadIdx.x;
#pragma unroll
    for (int k = 0; k < 8; ++k) {
        int idx = tid + 256 * k, line = idx >> 9, i = idx & 511;
        s[line][i] = make_float2(g_G[(size_t)(b * 512 + l0 + line) * 512 + i], 0.f);
    }
    __syncthreads();
    fft512x4(s, tid, +1.f);
#pragma unroll
    for (int k = 0; k < 8; ++k) {
        int idx = tid + 256 * k, line = idx >> 9, i = idx & 511;
        g_A[(size_t)(b * 512 + l0 + line) * 512 + i] = s[line][i];
    }
}

// ---- pass 4: inverse FFT along l of A_T columns -> pseudo[b][h][w] ---------
__global__ __launch_bounds__(256) void k_fft_cols_inv() {
    __shared__ float2 s[4][512];
    int bid = blockIdx.x;
    int b = bid >> 7, h0 = (bid & 127) << 2;
    int tid = threadIdx.x;
#pragma unroll
    for (int k = 0; k < 8; ++k) {
        int idx = tid + 256 * k;
        int line = idx & 3, i = idx >> 2;
        s[line][i] = g_A[(size_t)(b * 512 + i) * 512 + h0 + line];
    }
    __syncthreads();
    fft512x4(s, tid, +1.f);
#pragma unroll
    for (int k = 0; k < 8; ++k) {
        int idx = tid + 256 * k, line = idx >> 9, w = idx & 511;
        g_Pb[(size_t)(b * 512 + h0 + line) * 512 + w] = s[line][w].x;
    }
}

// ---- transpose pseudo [b][h][w] -> [h][w][b], fold ifft2 1/(H*W) -----------
__global__ __launch_bounds__(256) void k_transpose() {
    __shared__ float tile[256][17];
    int h = blockIdx.x >> 1;
    int w0 = (blockIdx.x & 1) << 8;
    int tid = threadIdx.x;
#pragma unroll
    for (int b = 0; b < 16; ++b)
        tile[tid][b] = g_Pb[(size_t)(b * 512 + h) * 512 + w0 + tid];
    __syncthreads();
    size_t base = ((size_t)h * 512 + w0) * 16;
    const float sc = 1.f / 262144.f;
    for (int j = tid; j < 4096; j += 256)
        g_Ph[base + j] = tile[j >> 4][j & 15] * sc;
}

// ---- fused mask generation + contraction -----------------------------------
// grid: (45 theta-groups of 4) x (16 h-splits of 32 rows); 256 threads
__global__ __launch_bounds__(256) void k_contract(const float* __restrict__ lp) {
    const int grp = blockIdx.x, spl = blockIdx.y, tid = threadIdx.x;
    const float lp0 = __ldg(lp), lp1 = __ldg(lp + 1), lp2 = __ldg(lp + 2);
    const float Ac = 2.f * (lp0 - lp1 + lp2);
    const float Bc = 2.f * (-5.f * lp0 + 4.f * lp1 - lp2);
    const float Cc = 8.f * lp0;
    const float s0 = 2.f * lp0;

    float ct[4], st_[4];
#pragma unroll
    for (int q = 0; q < 4; ++q) {
        int t = grp * 4 + q;
        float th = (float)((double)t * 0.017453292519943295);  // pi/180
        ct[q]  = cosf(th);
        st_[q] = sinf(th);
    }

    float acc[4][16];
#pragma unroll
    for (int q = 0; q < 4; ++q)
#pragma unroll
        for (int b = 0; b < 16; ++b) acc[q][b] = 0.f;

    const int h0 = spl * 32;
    for (int it = 0; it < 64; ++it) {           // 32 rows * 512 w / 256 thr
        int idx = it * 256 + tid;
        int hi = idx >> 9, w = idx & 511;
        int h = h0 + hi;
        float mf = (float)(h - ((h >= 256) ? 512 : 0));
        float nf = (float)(w - ((w >= 256) ? 512 : 0));

        const float4* p4 = reinterpret_cast<const float4*>(g_Ph + ((size_t)(h * 512 + w) << 4));
        float4 pa = p4[0], pb4 = p4[1], pc = p4[2], pd = p4[3];
        float pv[16] = {pa.x, pa.y, pa.z, pa.w, pb4.x, pb4.y, pb4.z, pb4.w,
                        pc.x, pc.y, pc.z, pc.w, pd.x, pd.y, pd.z, pd.w};

#pragma unroll
        for (int q = 0; q < 4; ++q) {
            float x = fmaf(mf, ct[q], nf * st_[q]);
            float u = x * x;
            float num = fmaf(fmaf(Ac, u, Bc), u, Cc);
            float den = x * (x - 1.f) * (x + 1.f) * (x - 2.f) * (x + 2.f);
            // sin(pi*x) with exact nearest-integer reduction (keeps relative
            // accuracy near sinc zeros, which the rational form divides by)
            int ki = __float2int_rn(x);
            float r = x - (float)ki;
            float sv = __sinf(PI_F * r);
            sv = (ki & 1) ? -sv : sv;
            float mask = __fdividef(sv * num, PI_F * den);
            if (den == 0.f) {  // x in {0,+-1,+-2} exactly -> sinc limits
                float ax = fabsf(x);
                mask = (ax == 0.f) ? s0 : ((ax == 1.f) ? lp1 : lp2);
            }
#pragma unroll
            for (int b = 0; b < 16; ++b)
                acc[q][b] = fmaf(mask, pv[b], acc[q][b]);
        }
    }

    // deterministic block reduction
#pragma unroll
    for (int q = 0; q < 4; ++q)
#pragma unroll
        for (int b = 0; b < 16; ++b)
#pragma unroll
            for (int off = 16; off > 0; off >>= 1)
                acc[q][b] += __shfl_down_sync(0xffffffffu, acc[q][b], off);

    __shared__ float red[8][64];
    int wid = tid >> 5, lid = tid & 31;
    if (lid == 0) {
#pragma unroll
        for (int q = 0; q < 4; ++q)
#pragma unroll
            for (int b = 0; b < 16; ++b)
                red[wid][q * 16 + b] = acc[q][b];
    }
    __syncthreads();
    if (tid < 64) {
        float sum = 0.f;
#pragma unroll
        for (int ww = 0; ww < 8; ++ww) sum += red[ww][tid];
        g_part[(grp * 16 + spl) * 64 + tid] = sum;
    }
}

// ---- final reduction over h-splits; fold einsum 1/(H*W) --------------------
__global__ __launch_bounds__(256) void k_reduce(float* __restrict__ out) {
    int i = blockIdx.x * 256 + threadIdx.x;
    if (i >= 45 * 64) return;
    int grp = i >> 6, qb = i & 63;
    int q = qb >> 4, b = qb & 15;
    float s = 0.f;
#pragma unroll
    for (int spl = 0; spl < 16; ++spl)
        s += g_part[(grp * 16 + spl) * 64 + qb];
    int t = grp * 4 + q;
    out[b * 180 + t] = s * (1.f / 262144.f);
}

// ---------------------------------------------------------------------------
extern "C" void kernel_launch(void* const* d_in, const int* in_sizes, int n_in,
                              void* d_out, int out_size) {
    const float* batch = (const float*)d_in[0];   // [16,256,256]
    const float* lp    = (const float*)d_in[1];   // [3]
    float* out         = (float*)d_out;           // [16,180]
    (void)in_sizes; (void)n_in; (void)out_size;

    k_fft_rows_fwd<<<1024, 256>>>(batch);
    k_fft_cols_fwd_abs<<<2048, 256>>>();
    k_fft_rows_inv<<<2048, 256>>>();
    k_fft_cols_inv<<<2048, 256>>>();
    k_transpose<<<1024, 256>>>();
    k_contract<<<dim3(45, 16), 256>>>(lp);
    k_reduce<<<12, 256>>>(out);
}

// round 3
// speedup vs baseline: 2.1866x; 2.1866x over previous
#include <cuda_runtime.h>
#include <math.h>

#define R2F 0.70710678118654752440f
#define PI_F 3.14159265358979f
#define LSTR 580   // padded per-line smem stride (float2 units), max padi(511)=574

// ---------------- scratch (static __device__, no allocation) ----------------
static __device__ float2 g_F1[16 * 256 * 512];
static __device__ float  g_G [16 * 512 * 512];
static __device__ float2 g_A [16 * 512 * 512];
static __device__ float  g_Pb[16 * 512 * 512];
static __device__ float  g_Pf[257 * 512 * 16];   // folded pseudo [h][w][b], h=0..256
static __device__ float  g_part[45 * 9 * 64];

__device__ __forceinline__ int padi(int i) { return i + (i >> 3); }

// ---------------- radix-8 building blocks -----------------------------------
template<int SGN>
__device__ __forceinline__ void fft8(float2 v[8]) {
    const float S = (float)SGN;
    float2 t;
#define BF(a,b) t=v[a]; v[a].x=t.x+v[b].x; v[a].y=t.y+v[b].y; v[b].x=t.x-v[b].x; v[b].y=t.y-v[b].y;
    BF(0,4) BF(1,5) BF(2,6) BF(3,7)
    { float2 a=v[5]; v[5]=make_float2(R2F*(a.x - S*a.y), R2F*(S*a.x + a.y)); }
    { float2 a=v[6]; v[6]=make_float2(-S*a.y, S*a.x); }
    { float2 a=v[7]; v[7]=make_float2(R2F*(-a.x - S*a.y), R2F*(S*a.x - a.y)); }
    BF(0,2) BF(1,3) BF(4,6) BF(5,7)
    { float2 a=v[3]; v[3]=make_float2(-S*a.y, S*a.x); }
    { float2 a=v[7]; v[7]=make_float2(-S*a.y, S*a.x); }
    BF(0,1) BF(2,3) BF(4,5) BF(6,7)
#undef BF
}

template<int SGN, int NS>
__device__ __forceinline__ void twiddle(float2 v[8], int j) {
    if (NS == 1) return;
    float base = (float)SGN * (6.283185307179586f / (float)(8 * NS)) * (float)(j & (NS - 1));
#pragma unroll
    for (int r = 1; r < 8; ++r) {
        float s, c; __sincosf(base * (float)r, &s, &c);
        float2 a = v[r];
        v[r] = make_float2(a.x * c - a.y * s, a.x * s + a.y * c);
    }
}

// DIF-core output is bit-reversed: X[k] = v[brev3(k)] with brev3 = 0,4,2,6,1,5,3,7
template<int NS>
__device__ __forceinline__ void store_stage(float2* dst, float2 v[8], int j) {
    int jd = ((j & ~(NS - 1)) << 3) + (j & (NS - 1));   // (j/NS)*NS*8 + j%NS
    dst[padi(jd)]          = v[0];
    dst[padi(jd + NS)]     = v[4];
    dst[padi(jd + 2 * NS)] = v[2];
    dst[padi(jd + 3 * NS)] = v[6];
    dst[padi(jd + 4 * NS)] = v[1];
    dst[padi(jd + 5 * NS)] = v[5];
    dst[padi(jd + 6 * NS)] = v[3];
    dst[padi(jd + 7 * NS)] = v[7];
}

__device__ __forceinline__ void load_stage(const float2* src, float2 v[8], int j) {
#pragma unroll
    for (int r = 0; r < 8; ++r) v[r] = src[padi(j + 64 * r)];
}

// ---- pass 1: forward FFT along w of zero-padded rows (only i<256 nonzero) --
__global__ __launch_bounds__(256) void k_fft_rows_fwd(const float* __restrict__ x) {
    __shared__ float2 sb[2][4][LSTR];
    int bid = blockIdx.x, b = bid >> 6, h0 = (bid & 63) << 2;
    int tid = threadIdx.x, line = tid >> 6, j = tid & 63;
    float2 v[8];
    const float* xr = x + (size_t)(b * 256 + h0 + line) * 256;
#pragma unroll
    for (int r = 0; r < 8; ++r)
        v[r] = (r < 4) ? make_float2(xr[j + 64 * r], 0.f) : make_float2(0.f, 0.f);
    fft8<-1>(v);
    store_stage<1>(&sb[0][line][0], v, j);
    __syncthreads();
    load_stage(&sb[0][line][0], v, j);
    twiddle<-1, 8>(v, j); fft8<-1>(v);
    store_stage<8>(&sb[1][line][0], v, j);
    __syncthreads();
    load_stage(&sb[1][line][0], v, j);
    twiddle<-1, 64>(v, j); fft8<-1>(v);
    float2* o = g_F1 + (size_t)(b * 256 + h0 + line) * 512;
    o[j] = v[0]; o[j + 64] = v[4]; o[j + 128] = v[2]; o[j + 192] = v[6];
    o[j + 256] = v[1]; o[j + 320] = v[5]; o[j + 384] = v[3]; o[j + 448] = v[7];
}

// ---- pass 2: forward FFT along h (upper half zeros), |F| -> G_T ------------
__global__ __launch_bounds__(256) void k_fft_cols_fwd_abs() {
    __shared__ float2 sb[2][4][LSTR];
    int bid = blockIdx.x, b = bid >> 7, l0 = (bid & 127) << 2;
    int tid = threadIdx.x, line = tid >> 6, j = tid & 63;
#pragma unroll
    for (int k = 0; k < 8; ++k) {
        int idx = tid + 256 * k, l4 = idx & 3, i = idx >> 2;
        float2 val = (i < 256) ? g_F1[(size_t)(b * 256 + i) * 512 + l0 + l4]
                               : make_float2(0.f, 0.f);
        sb[0][l4][padi(i)] = val;
    }
    __syncthreads();
    float2 v[8];
    load_stage(&sb[0][line][0], v, j);
    fft8<-1>(v);
    store_stage<1>(&sb[1][line][0], v, j);
    __syncthreads();
    load_stage(&sb[1][line][0], v, j);
    twiddle<-1, 8>(v, j); fft8<-1>(v);
    store_stage<8>(&sb[0][line][0], v, j);
    __syncthreads();
    load_stage(&sb[0][line][0], v, j);
    twiddle<-1, 64>(v, j); fft8<-1>(v);
    float* o = g_G + (size_t)(b * 512 + l0 + line) * 512;
    o[j]       = sqrtf(v[0].x * v[0].x + v[0].y * v[0].y);
    o[j + 64]  = sqrtf(v[4].x * v[4].x + v[4].y * v[4].y);
    o[j + 128] = sqrtf(v[2].x * v[2].x + v[2].y * v[2].y);
    o[j + 192] = sqrtf(v[6].x * v[6].x + v[6].y * v[6].y);
    o[j + 256] = sqrtf(v[1].x * v[1].x + v[1].y * v[1].y);
    o[j + 320] = sqrtf(v[5].x * v[5].x + v[5].y * v[5].y);
    o[j + 384] = sqrtf(v[3].x * v[3].x + v[3].y * v[3].y);
    o[j + 448] = sqrtf(v[7].x * v[7].x + v[7].y * v[7].y);
}

// ---- pass 3: inverse FFT along k of real G_T rows -> A_T -------------------
__global__ __launch_bounds__(256) void k_fft_rows_inv() {
    __shared__ float2 sb[2][4][LSTR];
    int bid = blockIdx.x, b = bid >> 7, l0 = (bid & 127) << 2;
    int tid = threadIdx.x, line = tid >> 6, j = tid & 63;
    float2 v[8];
    const float* gr = g_G + (size_t)(b * 512 + l0 + line) * 512;
#pragma unroll
    for (int r = 0; r < 8; ++r) v[r] = make_float2(gr[j + 64 * r], 0.f);
    fft8<1>(v);
    store_stage<1>(&sb[0][line][0], v, j);
    __syncthreads();
    load_stage(&sb[0][line][0], v, j);
    twiddle<1, 8>(v, j); fft8<1>(v);
    store_stage<8>(&sb[1][line][0], v, j);
    __syncthreads();
    load_stage(&sb[1][line][0], v, j);
    twiddle<1, 64>(v, j); fft8<1>(v);
    float2* o = g_A + (size_t)(b * 512 + l0 + line) * 512;
    o[j] = v[0]; o[j + 64] = v[4]; o[j + 128] = v[2]; o[j + 192] = v[6];
    o[j + 256] = v[1]; o[j + 320] = v[5]; o[j + 384] = v[3]; o[j + 448] = v[7];
}

// ---- pass 4: inverse FFT along l of A_T columns -> pseudo[b][h][w] ---------
__global__ __launch_bounds__(256) void k_fft_cols_inv() {
    __shared__ float2 sb[2][4][LSTR];
    int bid = blockIdx.x, b = bid >> 7, h0 = (bid & 127) << 2;
    int tid = threadIdx.x, line = tid >> 6, j = tid & 63;
#pragma unroll
    for (int k = 0; k < 8; ++k) {
        int idx = tid + 256 * k, l4 = idx & 3, i = idx >> 2;
        sb[0][l4][padi(i)] = g_A[(size_t)(b * 512 + i) * 512 + h0 + l4];
    }
    __syncthreads();
    float2 v[8];
    load_stage(&sb[0][line][0], v, j);
    fft8<1>(v);
    store_stage<1>(&sb[1][line][0], v, j);
    __syncthreads();
    load_stage(&sb[1][line][0], v, j);
    twiddle<1, 8>(v, j); fft8<1>(v);
    store_stage<8>(&sb[0][line][0], v, j);
    __syncthreads();
    load_stage(&sb[0][line][0], v, j);
    twiddle<1, 64>(v, j); fft8<1>(v);
    float* o = g_Pb + (size_t)(b * 512 + h0 + line) * 512;
    o[j] = v[0].x; o[j + 64] = v[4].x; o[j + 128] = v[2].x; o[j + 192] = v[6].x;
    o[j + 256] = v[1].x; o[j + 320] = v[5].x; o[j + 384] = v[3].x; o[j + 448] = v[7].x;
}

// ---- transpose + centrosymmetric fold: [b][h][w] -> [h][w][b], h=0..256 ----
// pseudo(h,w) == pseudo((-h)%512,(-w)%512) and mask is even in x, so fold pairs.
__global__ __launch_bounds__(256) void k_transpose_fold() {
    __shared__ float tile[256][17];
    int h = blockIdx.x >> 1, w0 = (blockIdx.x & 1) << 8;
    int tid = threadIdx.x, w = w0 + tid;
    const float sc = 1.f / 262144.f;
    bool fold = (h != 0) && (h != 256);
    int h2 = 512 - h, w2 = (512 - w) & 511;
#pragma unroll
    for (int b = 0; b < 16; ++b) {
        float a = g_Pb[(size_t)(b * 512 + h) * 512 + w];
        if (fold) a += g_Pb[(size_t)(b * 512 + h2) * 512 + w2];
        tile[tid][b] = a * sc;
    }
    __syncthreads();
    size_t base = ((size_t)h * 512 + w0) * 16;
    for (int jj = tid; jj < 4096; jj += 256)
        g_Pf[base + jj] = tile[jj >> 4][jj & 15];
}

// ---- fused mask generation + contraction over folded half-domain -----------
// grid: (45 theta-groups of 4) x (9 h-splits); splits 0-7 = 32 rows, split 8 = row 256
__global__ __launch_bounds__(256) void k_contract(const float* __restrict__ lp) {
    const int grp = blockIdx.x, spl = blockIdx.y, tid = threadIdx.x;
    const float lp0 = __ldg(lp), lp1 = __ldg(lp + 1), lp2 = __ldg(lp + 2);
    const float Ac = 2.f * (lp0 - lp1 + lp2);
    const float Bc = 2.f * (-5.f * lp0 + 4.f * lp1 - lp2);
    const float Cc = 8.f * lp0;
    const float s0 = 2.f * lp0;

    float ct[4], st_[4];
#pragma unroll
    for (int q = 0; q < 4; ++q) {
        int t = grp * 4 + q;
        float th = (float)((double)t * 0.017453292519943295);  // pi/180
        ct[q] = cosf(th);
        st_[q] = sinf(th);
    }

    float acc[4][16];
#pragma unroll
    for (int q = 0; q < 4; ++q)
#pragma unroll
        for (int b = 0; b < 16; ++b) acc[q][b] = 0.f;

    const int h0 = spl * 32;
    const int nit = (spl < 8) ? 64 : 2;
    for (int it = 0; it < nit; ++it) {
        int idx = it * 256 + tid;
        int hi = idx >> 9, w = idx & 511;
        int h = h0 + hi;
        float mf = (float)(h - ((h >= 256) ? 512 : 0));
        float nf = (float)(w - ((w >= 256) ? 512 : 0));

        const float4* p4 = reinterpret_cast<const float4*>(g_Pf + ((size_t)(h * 512 + w) << 4));
        float4 pa = p4[0], pb4 = p4[1], pc = p4[2], pd = p4[3];
        float pv[16] = {pa.x, pa.y, pa.z, pa.w, pb4.x, pb4.y, pb4.z, pb4.w,
                        pc.x, pc.y, pc.z, pc.w, pd.x, pd.y, pd.z, pd.w};

#pragma unroll
        for (int q = 0; q < 4; ++q) {
            float x = fmaf(mf, ct[q], nf * st_[q]);
            float u = x * x;
            float num = fmaf(fmaf(Ac, u, Bc), u, Cc);
            float den = x * (x - 1.f) * (x + 1.f) * (x - 2.f) * (x + 2.f);
            int ki = __float2int_rn(x);
            float r = x - (float)ki;
            float sv = __sinf(PI_F * r);
            sv = (ki & 1) ? -sv : sv;
            float mask = __fdividef(sv * num, PI_F * den);
            if (den == 0.f) {  // x in {0,+-1,+-2} exactly -> sinc limits
                float ax = fabsf(x);
                mask = (ax == 0.f) ? s0 : ((ax == 1.f) ? lp1 : lp2);
            }
#pragma unroll
            for (int b = 0; b < 16; ++b)
                acc[q][b] = fmaf(mask, pv[b], acc[q][b]);
        }
    }

    // deterministic block reduction
#pragma unroll
    for (int q = 0; q < 4; ++q)
#pragma unroll
        for (int b = 0; b < 16; ++b)
#pragma unroll
            for (int off = 16; off > 0; off >>= 1)
                acc[q][b] += __shfl_down_sync(0xffffffffu, acc[q][b], off);

    __shared__ float red[8][64];
    int wid = tid >> 5, lid = tid & 31;
    if (lid == 0) {
#pragma unroll
        for (int q = 0; q < 4; ++q)
#pragma unroll
            for (int b = 0; b < 16; ++b)
                red[wid][q * 16 + b] = acc[q][b];
    }
    __syncthreads();
    if (tid < 64) {
        float sum = 0.f;
#pragma unroll
        for (int ww = 0; ww < 8; ++ww) sum += red[ww][tid];
        g_part[(grp * 9 + spl) * 64 + tid] = sum;
    }
}

// ---- final reduction over h-splits; fold einsum 1/(H*W) --------------------
__global__ __launch_bounds__(256) void k_reduce(float* __restrict__ out) {
    int i = blockIdx.x * 256 + threadIdx.x;
    if (i >= 45 * 64) return;
    int grp = i >> 6, qb = i & 63;
    int q = qb >> 4, b = qb & 15;
    float s = 0.f;
#pragma unroll
    for (int spl = 0; spl < 9; ++spl)
        s += g_part[(grp * 9 + spl) * 64 + qb];
    int t = grp * 4 + q;
    out[b * 180 + t] = s * (1.f / 262144.f);
}

// ---------------------------------------------------------------------------
extern "C" void kernel_launch(void* const* d_in, const int* in_sizes, int n_in,
                              void* d_out, int out_size) {
    const float* batch = (const float*)d_in[0];   // [16,256,256]
    const float* lp    = (const float*)d_in[1];   // [3]
    float* out         = (float*)d_out;           // [16,180]
    (void)in_sizes; (void)n_in; (void)out_size;

    k_fft_rows_fwd<<<1024, 256>>>(batch);
    k_fft_cols_fwd_abs<<<2048, 256>>>();
    k_fft_rows_inv<<<2048, 256>>>();
    k_fft_cols_inv<<<2048, 256>>>();
    k_transpose_fold<<<514, 256>>>();
    k_contract<<<dim3(45, 9), 256>>>(lp);
    k_reduce<<<12, 256>>>(out);
}

// round 5
// speedup vs baseline: 3.1237x; 1.4286x over previous
#include <cuda_runtime.h>
#include <math.h>

#define R2F 0.70710678118654752440f
#define PI_F 3.14159265358979f
#define LSTR 580   // padded per-line smem stride (float2 units)
#define F1S  264   // g_F1 row stride (float2), cols 0..256 used

// ---------------- scratch (static __device__, zero-init, no allocation) -----
static __device__ float2 g_F1[16 * 256 * F1S];   // row-FFT, k=0..256 only
static __device__ float  g_G [16 * 260 * 512];   // |F| as [b][k<=256][l]
static __device__ float2 g_A [16 * 257 * 512];   // A[b][k<=256][h]
static __device__ float  g_Pb[16 * 512 * 512];   // pseudo[b][h][w]
static __device__ float  g_Pf[257 * 512 * 16];   // folded pseudo [h][w][b]
static __device__ float  g_c256[512 * 16];       // unfolded column w=256, scaled
static __device__ float  g_part[23 * 17 * 128];  // [grp][spl][sign*64+q*16+b]

__device__ __forceinline__ int padi(int i) { return i + (i >> 3); }

// ---------------- radix-8 building blocks -----------------------------------
template<int SGN>
__device__ __forceinline__ void fft8(float2 v[8]) {
    const float S = (float)SGN;
    float2 t;
#define BF(a,b) t=v[a]; v[a].x=t.x+v[b].x; v[a].y=t.y+v[b].y; v[b].x=t.x-v[b].x; v[b].y=t.y-v[b].y;
    BF(0,4) BF(1,5) BF(2,6) BF(3,7)
    { float2 a=v[5]; v[5]=make_float2(R2F*(a.x - S*a.y), R2F*(S*a.x + a.y)); }
    { float2 a=v[6]; v[6]=make_float2(-S*a.y, S*a.x); }
    { float2 a=v[7]; v[7]=make_float2(R2F*(-a.x - S*a.y), R2F*(S*a.x - a.y)); }
    BF(0,2) BF(1,3) BF(4,6) BF(5,7)
    { float2 a=v[3]; v[3]=make_float2(-S*a.y, S*a.x); }
    { float2 a=v[7]; v[7]=make_float2(-S*a.y, S*a.x); }
    BF(0,1) BF(2,3) BF(4,5) BF(6,7)
#undef BF
}

template<int SGN, int NS>
__device__ __forceinline__ void twiddle(float2 v[8], int j) {
    if (NS == 1) return;
    float base = (float)SGN * (6.283185307179586f / (float)(8 * NS)) * (float)(j & (NS - 1));
#pragma unroll
    for (int r = 1; r < 8; ++r) {
        float s, c; __sincosf(base * (float)r, &s, &c);
        float2 a = v[r];
        v[r] = make_float2(a.x * c - a.y * s, a.x * s + a.y * c);
    }
}

template<int NS>
__device__ __forceinline__ void store_stage(float2* dst, float2 v[8], int j) {
    int jd = ((j & ~(NS - 1)) << 3) + (j & (NS - 1));
    dst[padi(jd)]          = v[0];
    dst[padi(jd + NS)]     = v[4];
    dst[padi(jd + 2 * NS)] = v[2];
    dst[padi(jd + 3 * NS)] = v[6];
    dst[padi(jd + 4 * NS)] = v[1];
    dst[padi(jd + 5 * NS)] = v[5];
    dst[padi(jd + 6 * NS)] = v[3];
    dst[padi(jd + 7 * NS)] = v[7];
}

__device__ __forceinline__ void load_stage(const float2* src, float2 v[8], int j) {
#pragma unroll
    for (int r = 0; r < 8; ++r) v[r] = src[padi(j + 64 * r)];
}

// ---- pass 1: row FFT of zero-padded real rows; store only k<=256 -----------
__global__ __launch_bounds__(256) void k_fft_rows_fwd(const float* __restrict__ x) {
    __shared__ float2 sb[2][4][LSTR];
    int bid = blockIdx.x, b = bid >> 6, h0 = (bid & 63) << 2;
    int tid = threadIdx.x, line = tid >> 6, j = tid & 63;
    float2 v[8];
    const float* xr = x + (size_t)(b * 256 + h0 + line) * 256;
#pragma unroll
    for (int r = 0; r < 8; ++r)
        v[r] = (r < 4) ? make_float2(xr[j + 64 * r], 0.f) : make_float2(0.f, 0.f);
    fft8<-1>(v);
    store_stage<1>(&sb[0][line][0], v, j);
    __syncthreads();
    load_stage(&sb[0][line][0], v, j);
    twiddle<-1, 8>(v, j); fft8<-1>(v);
    store_stage<8>(&sb[1][line][0], v, j);
    __syncthreads();
    load_stage(&sb[1][line][0], v, j);
    twiddle<-1, 64>(v, j); fft8<-1>(v);
    float2* o = g_F1 + (size_t)(b * 256 + h0 + line) * F1S;
    o[j] = v[0]; o[j + 64] = v[4]; o[j + 128] = v[2]; o[j + 192] = v[6];
    if (j == 0) o[256] = v[1];          // pos 256; all pos>256 discarded (Hermitian)
}

// ---- pass 2: column FFT over h for k=0..256 only; store |F| ----------------
__global__ __launch_bounds__(256) void k_fft_cols_fwd_abs() {
    __shared__ float2 sb[2][4][LSTR];
    int bid = blockIdx.x, b = bid / 65, cg = bid % 65, kcb = cg << 2;
    int tid = threadIdx.x, line = tid >> 6, j = tid & 63;
#pragma unroll
    for (int k = 0; k < 8; ++k) {
        int idx = tid + 256 * k, l4 = idx & 3, i = idx >> 2;
        int kc = kcb + l4;
        float2 val = (i < 256 && kc <= 256)
                   ? g_F1[(size_t)(b * 256 + i) * F1S + kc] : make_float2(0.f, 0.f);
        sb[0][l4][padi(i)] = val;
    }
    __syncthreads();
    float2 v[8];
    load_stage(&sb[0][line][0], v, j);
    fft8<-1>(v);
    store_stage<1>(&sb[1][line][0], v, j);
    __syncthreads();
    load_stage(&sb[1][line][0], v, j);
    twiddle<-1, 8>(v, j); fft8<-1>(v);
    store_stage<8>(&sb[0][line][0], v, j);
    __syncthreads();
    load_stage(&sb[0][line][0], v, j);
    twiddle<-1, 64>(v, j); fft8<-1>(v);
    int kc = kcb + line;
    if (kc <= 256) {
        float* o = g_G + (size_t)(b * 260 + kc) * 512;
        o[j]       = sqrtf(v[0].x * v[0].x + v[0].y * v[0].y);
        o[j + 64]  = sqrtf(v[4].x * v[4].x + v[4].y * v[4].y);
        o[j + 128] = sqrtf(v[2].x * v[2].x + v[2].y * v[2].y);
        o[j + 192] = sqrtf(v[6].x * v[6].x + v[6].y * v[6].y);
        o[j + 256] = sqrtf(v[1].x * v[1].x + v[1].y * v[1].y);
        o[j + 320] = sqrtf(v[5].x * v[5].x + v[5].y * v[5].y);
        o[j + 384] = sqrtf(v[3].x * v[3].x + v[3].y * v[3].y);
        o[j + 448] = sqrtf(v[7].x * v[7].x + v[7].y * v[7].y);
    }
}

// ---- pass 3: inverse FFT over l of real G rows k=0..256 -> A[b][k][h] ------
__global__ __launch_bounds__(256) void k_fft_rows_inv() {
    __shared__ float2 sb[2][4][LSTR];
    int bid = blockIdx.x, b = bid / 65, cg = bid % 65, kr = (cg << 2) + (threadIdx.x >> 6);
    int tid = threadIdx.x, line = tid >> 6, j = tid & 63;
    float2 v[8];
    const float* gr = g_G + (size_t)(b * 260 + kr) * 512;   // rows 257..259 stay zero
#pragma unroll
    for (int r = 0; r < 8; ++r) v[r] = make_float2(gr[j + 64 * r], 0.f);
    fft8<1>(v);
    store_stage<1>(&sb[0][line][0], v, j);
    __syncthreads();
    load_stage(&sb[0][line][0], v, j);
    twiddle<1, 8>(v, j); fft8<1>(v);
    store_stage<8>(&sb[1][line][0], v, j);
    __syncthreads();
    load_stage(&sb[1][line][0], v, j);
    twiddle<1, 64>(v, j); fft8<1>(v);
    if (kr <= 256) {
        float2* o = g_A + (size_t)(b * 257 + kr) * 512;
        o[j] = v[0]; o[j + 64] = v[4]; o[j + 128] = v[2]; o[j + 192] = v[6];
        o[j + 256] = v[1]; o[j + 320] = v[5]; o[j + 384] = v[3]; o[j + 448] = v[7];
    }
}

// ---- pass 4: packed inverse FFT over k (2 h-columns per FFT, Hermitian) ----
__global__ __launch_bounds__(256) void k_fft_cols_inv() {
    __shared__ float2 sb[2][4][LSTR];
    int bid = blockIdx.x, b = bid >> 6, h0 = (bid & 63) << 3;
    int tid = threadIdx.x, line = tid >> 6, j = tid & 63;
    // build s[u][k] = A[k][h0+2u] + i*A[k][h0+2u+1]; k>256 via conj symmetry
#pragma unroll
    for (int it = 0; it < 8; ++it) {
        int idx = it * 256 + tid, u = idx & 3, kk = idx >> 2;
        float2 sv;
        if (kk <= 256) {
            const float4 q4 = *reinterpret_cast<const float4*>(
                g_A + (size_t)(b * 257 + kk) * 512 + h0 + 2 * u);
            sv = make_float2(q4.x - q4.w, q4.y + q4.z);
        } else {
            int k2 = 512 - kk;
            const float4 q4 = *reinterpret_cast<const float4*>(
                g_A + (size_t)(b * 257 + k2) * 512 + h0 + 2 * u);
            sv = make_float2(q4.x + q4.w, q4.z - q4.y);
        }
        sb[0][u][padi(kk)] = sv;
    }
    __syncthreads();
    float2 v[8];
    load_stage(&sb[0][line][0], v, j);
    fft8<1>(v);
    store_stage<1>(&sb[1][line][0], v, j);
    __syncthreads();
    load_stage(&sb[1][line][0], v, j);
    twiddle<1, 8>(v, j); fft8<1>(v);
    store_stage<8>(&sb[0][line][0], v, j);
    __syncthreads();
    load_stage(&sb[0][line][0], v, j);
    twiddle<1, 64>(v, j); fft8<1>(v);
    float* o1 = g_Pb + (size_t)(b * 512 + h0 + 2 * line) * 512;
    float* o2 = o1 + 512;
    o1[j] = v[0].x;       o2[j] = v[0].y;
    o1[j + 64] = v[4].x;  o2[j + 64] = v[4].y;
    o1[j + 128] = v[2].x; o2[j + 128] = v[2].y;
    o1[j + 192] = v[6].x; o2[j + 192] = v[6].y;
    o1[j + 256] = v[1].x; o2[j + 256] = v[1].y;
    o1[j + 320] = v[5].x; o2[j + 320] = v[5].y;
    o1[j + 384] = v[3].x; o2[j + 384] = v[3].y;
    o1[j + 448] = v[7].x; o2[j + 448] = v[7].y;
}

// ---- transpose + centro fold; half-weight w=0; also fill column-256 copy ---
__global__ __launch_bounds__(256) void k_transpose_fold() {
    int bid = blockIdx.x, tid = threadIdx.x;
    const float sc = 1.f / 262144.f;
    if (bid >= 514) {                         // g_c256 fill: h = 0..511
        int hh = (bid - 514) * 256 + tid;
#pragma unroll
        for (int b = 0; b < 16; ++b)
            g_c256[hh * 16 + b] = g_Pb[((size_t)(b * 512 + hh)) * 512 + 256] * sc;
        return;
    }
    __shared__ float tile[256][17];
    int h = bid >> 1, w0 = (bid & 1) << 8;
    int w = w0 + tid;
    bool fold = (h != 0) && (h != 256);
    int h2 = 512 - h, w2 = (512 - w) & 511;
    float wgt = (w == 0) ? 0.5f * sc : sc;    // w=0 self-pairs in contract
#pragma unroll
    for (int b = 0; b < 16; ++b) {
        float a = g_Pb[(size_t)(b * 512 + h) * 512 + w];
        if (fold) a += g_Pb[(size_t)(b * 512 + h2) * 512 + w2];
        tile[tid][b] = a * wgt;
    }
    __syncthreads();
    size_t base = ((size_t)h * 512 + w0) * 16;
    for (int jj = tid; jj < 4096; jj += 256)
        g_Pf[base + jj] = tile[jj >> 4][jj & 15];
}

// ---- mask evaluator: lp0*s(x,0)+lp1*s(x,1)+lp2*s(x,2), rational closed form -
struct MaskC { float Ac, Bc, Cc, s0, l1, l2; };
__device__ __forceinline__ float mask_eval(float x, const MaskC& C) {
    float u = x * x;
    float num = fmaf(fmaf(C.Ac, u, C.Bc), u, C.Cc);
    float den = x * (x - 1.f) * (x + 1.f) * (x - 2.f) * (x + 2.f);
    int ki = __float2int_rn(x);
    float r = x - (float)ki;
    float sv = __sinf(PI_F * r);
    sv = (ki & 1) ? -sv : sv;
    float m = __fdividef(sv * num, PI_F * den);
    if (den == 0.f) {
        float ax = fabsf(x);
        m = (ax == 0.f) ? C.s0 : ((ax == 1.f) ? C.l1 : C.l2);
    }
    return m;
}

// ---- fused mask+contraction: 4 base thetas -> 8 effective via w-mirror ------
// grid (23, 17): spl 0..15 = 16 h-rows each (h=0..255, w'=0..255 paired with 512-w');
// spl 16 = tail: row h=256 (paired) + exact column w=256 from g_c256.
__global__ __launch_bounds__(256) void k_contract(const float* __restrict__ lp) {
    const int grp = blockIdx.x, spl = blockIdx.y, tid = threadIdx.x;
    const float lp0 = __ldg(lp), lp1 = __ldg(lp + 1), lp2 = __ldg(lp + 2);
    MaskC C;
    C.Ac = 2.f * (lp0 - lp1 + lp2);
    C.Bc = 2.f * (-5.f * lp0 + 4.f * lp1 - lp2);
    C.Cc = 8.f * lp0;
    C.s0 = 2.f * lp0; C.l1 = lp1; C.l2 = lp2;

    float ct[4], st_[4];
#pragma unroll
    for (int q = 0; q < 4; ++q) {
        float th = (float)((double)(grp * 4 + q) * 0.017453292519943295);
        ct[q] = cosf(th);
        st_[q] = sinf(th);
    }

    float accp[64], accm[64];
#pragma unroll
    for (int i = 0; i < 64; ++i) { accp[i] = 0.f; accm[i] = 0.f; }

    if (spl < 16) {
        const int h0 = spl * 16;
#pragma unroll 1
        for (int it = 0; it < 16; ++it) {
            int idx = it * 256 + tid;
            int hi = idx >> 8, wp = idx & 255;
            float mf = (float)(h0 + hi);
            float nf = (float)wp;
            int wB = (512 - wp) & 511;

            const float4* pa4 = reinterpret_cast<const float4*>(
                g_Pf + (((size_t)(h0 + hi) * 512 + wp) << 4));
            const float4* pb4 = reinterpret_cast<const float4*>(
                g_Pf + (((size_t)(h0 + hi) * 512 + wB) << 4));
            float4 a0 = pa4[0], a1 = pa4[1], a2 = pa4[2], a3 = pa4[3];
            float4 b0 = pb4[0], b1 = pb4[1], b2 = pb4[2], b3 = pb4[3];
            float pA[16] = {a0.x,a0.y,a0.z,a0.w, a1.x,a1.y,a1.z,a1.w,
                            a2.x,a2.y,a2.z,a2.w, a3.x,a3.y,a3.z,a3.w};
            float pB[16] = {b0.x,b0.y,b0.z,b0.w, b1.x,b1.y,b1.z,b1.w,
                            b2.x,b2.y,b2.z,b2.w, b3.x,b3.y,b3.z,b3.w};

            float Mp[4], Mm[4];
#pragma unroll
            for (int q = 0; q < 4; ++q) {
                Mp[q] = mask_eval(fmaf(mf, ct[q],  nf * st_[q]), C);
                Mm[q] = mask_eval(fmaf(mf, ct[q], -nf * st_[q]), C);
            }
#pragma unroll
            for (int q = 0; q < 4; ++q)
#pragma unroll
                for (int b = 0; b < 16; ++b) {
                    accp[q * 16 + b] = fmaf(Mp[q], pA[b], fmaf(Mm[q], pB[b], accp[q * 16 + b]));
                    accm[q * 16 + b] = fmaf(Mm[q], pA[b], fmaf(Mp[q], pB[b], accm[q * 16 + b]));
                }
        }
    } else {
        // (a) row h=256, paired over w'=0..255
        {
            int wp = tid;
            float mf = -256.f, nf = (float)wp;
            int wB = (512 - wp) & 511;
            const float4* pa4 = reinterpret_cast<const float4*>(
                g_Pf + (((size_t)256 * 512 + wp) << 4));
            const float4* pb4 = reinterpret_cast<const float4*>(
                g_Pf + (((size_t)256 * 512 + wB) << 4));
            float4 a0 = pa4[0], a1 = pa4[1], a2 = pa4[2], a3 = pa4[3];
            float4 b0 = pb4[0], b1 = pb4[1], b2 = pb4[2], b3 = pb4[3];
            float pA[16] = {a0.x,a0.y,a0.z,a0.w, a1.x,a1.y,a1.z,a1.w,
                            a2.x,a2.y,a2.z,a2.w, a3.x,a3.y,a3.z,a3.w};
            float pB[16] = {b0.x,b0.y,b0.z,b0.w, b1.x,b1.y,b1.z,b1.w,
                            b2.x,b2.y,b2.z,b2.w, b3.x,b3.y,b3.z,b3.w};
#pragma unroll
            for (int q = 0; q < 4; ++q) {
                float Mp = mask_eval(fmaf(mf, ct[q],  nf * st_[q]), C);
                float Mm = mask_eval(fmaf(mf, ct[q], -nf * st_[q]), C);
#pragma unroll
                for (int b = 0; b < 16; ++b) {
                    accp[q * 16 + b] = fmaf(Mp, pA[b], fmaf(Mm, pB[b], accp[q * 16 + b]));
                    accm[q * 16 + b] = fmaf(Mm, pA[b], fmaf(Mp, pB[b], accm[q * 16 + b]));
                }
            }
        }
        // (b) column w=256, all h=0..511, exact (unfolded, unpaired)
#pragma unroll 1
        for (int it = 0; it < 2; ++it) {
            int h = it * 256 + tid;
            float mf = (float)(h - ((h >= 256) ? 512 : 0));
            float nf = -256.f;
            const float4* pc4 = reinterpret_cast<const float4*>(g_c256 + h * 16);
            float4 c0 = pc4[0], c1 = pc4[1], c2 = pc4[2], c3 = pc4[3];
            float P[16] = {c0.x,c0.y,c0.z,c0.w, c1.x,c1.y,c1.z,c1.w,
                           c2.x,c2.y,c2.z,c2.w, c3.x,c3.y,c3.z,c3.w};
#pragma unroll
            for (int q = 0; q < 4; ++q) {
                float Mp = mask_eval(fmaf( mf, ct[q], nf * st_[q]), C);   // theta t
                float Mm = mask_eval(fmaf(-mf, ct[q], nf * st_[q]), C);   // theta 180-t
#pragma unroll
                for (int b = 0; b < 16; ++b) {
                    accp[q * 16 + b] = fmaf(Mp, P[b], accp[q * 16 + b]);
                    accm[q * 16 + b] = fmaf(Mm, P[b], accm[q * 16 + b]);
                }
            }
        }
    }

    // deterministic reduction: warp shuffles then smem
#pragma unroll
    for (int i = 0; i < 64; ++i) {
#pragma unroll
        for (int off = 16; off > 0; off >>= 1) {
            accp[i] += __shfl_down_sync(0xffffffffu, accp[i], off);
            accm[i] += __shfl_down_sync(0xffffffffu, accm[i], off);
        }
    }
    __shared__ float red[8][128];
    int wid = tid >> 5, lid = tid & 31;
    if (lid == 0) {
#pragma unroll
        for (int i = 0; i < 64; ++i) {
            red[wid][i] = accp[i];
            red[wid][64 + i] = accm[i];
        }
    }
    __syncthreads();
    if (tid < 128) {
        float s = 0.f;
#pragma unroll
        for (int w8 = 0; w8 < 8; ++w8) s += red[w8][tid];
        g_part[((size_t)grp * 17 + spl) * 128 + tid] = s;
    }
}

// ---- final reduction: map (grp,q,sign) slots -> t; fold einsum 1/(H*W) -----
__global__ __launch_bounds__(256) void k_reduce(float* __restrict__ out) {
    int i = blockIdx.x * 256 + threadIdx.x;
    if (i >= 2880) return;
    int t = i % 180, b = i / 180;
    int bt, sign;
    if (t <= 90) { bt = t; sign = 0; }
    else         { bt = 180 - t; sign = 1; }
    int grp = bt >> 2, q = bt & 3;
    int off = sign * 64 + q * 16 + b;
    float s = 0.f;
#pragma unroll
    for (int spl = 0; spl < 17; ++spl)
        s += g_part[((size_t)grp * 17 + spl) * 128 + off];
    out[b * 180 + t] = s * (1.f / 262144.f);
}

// ---------------------------------------------------------------------------
extern "C" void kernel_launch(void* const* d_in, const int* in_sizes, int n_in,
                              void* d_out, int out_size) {
    const float* batch = (const float*)d_in[0];   // [16,256,256]
    const float* lp    = (const float*)d_in[1];   // [3]
    float* out         = (float*)d_out;           // [16,180]
    (void)in_sizes; (void)n_in; (void)out_size;

    k_fft_rows_fwd<<<1024, 256>>>(batch);
    k_fft_cols_fwd_abs<<<1040, 256>>>();
    k_fft_rows_inv<<<1040, 256>>>();
    k_fft_cols_inv<<<1024, 256>>>();
    k_transpose_fold<<<516, 256>>>();
    k_contract<<<dim3(23, 17), 256>>>(lp);
    k_reduce<<<12, 256>>>(out);
}

// round 7
// speedup vs baseline: 3.2512x; 1.0408x over previous
#include <cuda_runtime.h>
#include <math.h>

#define R2F 0.70710678118654752440f
#define PI_F 3.14159265358979f
#define LSTR 580   // padded per-line smem stride (float2 units)
#define F1S  264   // g_F1 row stride (float2), cols 0..256 used

// ---------------- scratch (static __device__, zero-init, no allocation) -----
static __device__ float2 g_F1[16 * 256 * F1S];   // row-FFT, k=0..256 only
static __device__ float2 g_A [16 * 257 * 512];   // A[b][k<=256][h] (ifft over l of |F|)
static __device__ float  g_Pb[16 * 264 * 512];   // pseudo[b][h<=263][w]
static __device__ float  g_Pf[257 * 512 * 16];   // folded pseudo [h][w][b] (2x interior)
static __device__ float  g_c256[512 * 16];       // column w=256, all h, scaled
static __device__ float  g_part[23 * 17 * 128];  // [grp][spl][sign*64+q*16+b]

__device__ __forceinline__ int padi(int i) { return i + (i >> 3); }

// ---------------- radix-8 building blocks -----------------------------------
template<int SGN>
__device__ __forceinline__ void fft8(float2 v[8]) {
    const float S = (float)SGN;
    float2 t;
#define BF(a,b) t=v[a]; v[a].x=t.x+v[b].x; v[a].y=t.y+v[b].y; v[b].x=t.x-v[b].x; v[b].y=t.y-v[b].y;
    BF(0,4) BF(1,5) BF(2,6) BF(3,7)
    { float2 a=v[5]; v[5]=make_float2(R2F*(a.x - S*a.y), R2F*(S*a.x + a.y)); }
    { float2 a=v[6]; v[6]=make_float2(-S*a.y, S*a.x); }
    { float2 a=v[7]; v[7]=make_float2(R2F*(-a.x - S*a.y), R2F*(S*a.x - a.y)); }
    BF(0,2) BF(1,3) BF(4,6) BF(5,7)
    { float2 a=v[3]; v[3]=make_float2(-S*a.y, S*a.x); }
    { float2 a=v[7]; v[7]=make_float2(-S*a.y, S*a.x); }
    BF(0,1) BF(2,3) BF(4,5) BF(6,7)
#undef BF
}

template<int SGN, int NS>
__device__ __forceinline__ void twiddle(float2 v[8], int j) {
    if (NS == 1) return;
    float base = (float)SGN * (6.283185307179586f / (float)(8 * NS)) * (float)(j & (NS - 1));
#pragma unroll
    for (int r = 1; r < 8; ++r) {
        float s, c; __sincosf(base * (float)r, &s, &c);
        float2 a = v[r];
        v[r] = make_float2(a.x * c - a.y * s, a.x * s + a.y * c);
    }
}

template<int NS>
__device__ __forceinline__ void store_stage(float2* dst, float2 v[8], int j) {
    int jd = ((j & ~(NS - 1)) << 3) + (j & (NS - 1));
    dst[padi(jd)]          = v[0];
    dst[padi(jd + NS)]     = v[4];
    dst[padi(jd + 2 * NS)] = v[2];
    dst[padi(jd + 3 * NS)] = v[6];
    dst[padi(jd + 4 * NS)] = v[1];
    dst[padi(jd + 5 * NS)] = v[5];
    dst[padi(jd + 6 * NS)] = v[3];
    dst[padi(jd + 7 * NS)] = v[7];
}

__device__ __forceinline__ void load_stage(const float2* src, float2 v[8], int j) {
#pragma unroll
    for (int r = 0; r < 8; ++r) v[r] = src[padi(j + 64 * r)];
}

// ---- pass 1: row FFT of zero-padded real rows; store only k<=256 -----------
__global__ __launch_bounds__(256) void k_fft_rows_fwd(const float* __restrict__ x) {
    __shared__ float2 sb[2][4][LSTR];
    int bid = blockIdx.x, b = bid >> 6, h0 = (bid & 63) << 2;
    int tid = threadIdx.x, line = tid >> 6, j = tid & 63;
    float2 v[8];
    const float* xr = x + (size_t)(b * 256 + h0 + line) * 256;
#pragma unroll
    for (int r = 0; r < 8; ++r)
        v[r] = (r < 4) ? make_float2(xr[j + 64 * r], 0.f) : make_float2(0.f, 0.f);
    fft8<-1>(v);
    store_stage<1>(&sb[0][line][0], v, j);
    __syncthreads();
    load_stage(&sb[0][line][0], v, j);
    twiddle<-1, 8>(v, j); fft8<-1>(v);
    store_stage<8>(&sb[1][line][0], v, j);
    __syncthreads();
    load_stage(&sb[1][line][0], v, j);
    twiddle<-1, 64>(v, j); fft8<-1>(v);
    float2* o = g_F1 + (size_t)(b * 256 + h0 + line) * F1S;
    o[j] = v[0]; o[j + 64] = v[4]; o[j + 128] = v[2]; o[j + 192] = v[6];
    if (j == 0) o[256] = v[1];          // pos 256; pos>256 discarded (Hermitian)
}

// ---- pass 2+3 fused: FFT over h, |.|, inverse FFT over l, all in one block -
// For k-columns kc=0..256: A[b][kc][h] = ifft_l( |fft_h(F1[:,kc])| )
__global__ __launch_bounds__(256) void k_fft_cols_absinv() {
    __shared__ float2 sb[2][4][LSTR];
    int bid = blockIdx.x, b = bid / 65, cg = bid % 65, kcb = cg << 2;
    int tid = threadIdx.x, line = tid >> 6, j = tid & 63;
#pragma unroll
    for (int k = 0; k < 8; ++k) {
        int idx = tid + 256 * k, l4 = idx & 3, i = idx >> 2;
        int kc = kcb + l4;
        float2 val = (i < 256 && kc <= 256)
                   ? g_F1[(size_t)(b * 256 + i) * F1S + kc] : make_float2(0.f, 0.f);
        sb[0][l4][padi(i)] = val;
    }
    __syncthreads();
    float2 v[8];
    // forward FFT over h
    load_stage(&sb[0][line][0], v, j);
    fft8<-1>(v);
    store_stage<1>(&sb[1][line][0], v, j);
    __syncthreads();
    load_stage(&sb[1][line][0], v, j);
    twiddle<-1, 8>(v, j); fft8<-1>(v);
    store_stage<8>(&sb[0][line][0], v, j);
    __syncthreads();
    load_stage(&sb[0][line][0], v, j);
    twiddle<-1, 64>(v, j); fft8<-1>(v);
    __syncthreads();
    // |F| directly back to natural l-positions in smem
    sb[1][line][padi(j)]       = make_float2(sqrtf(v[0].x*v[0].x + v[0].y*v[0].y), 0.f);
    sb[1][line][padi(j + 64)]  = make_float2(sqrtf(v[4].x*v[4].x + v[4].y*v[4].y), 0.f);
    sb[1][line][padi(j + 128)] = make_float2(sqrtf(v[2].x*v[2].x + v[2].y*v[2].y), 0.f);
    sb[1][line][padi(j + 192)] = make_float2(sqrtf(v[6].x*v[6].x + v[6].y*v[6].y), 0.f);
    sb[1][line][padi(j + 256)] = make_float2(sqrtf(v[1].x*v[1].x + v[1].y*v[1].y), 0.f);
    sb[1][line][padi(j + 320)] = make_float2(sqrtf(v[5].x*v[5].x + v[5].y*v[5].y), 0.f);
    sb[1][line][padi(j + 384)] = make_float2(sqrtf(v[3].x*v[3].x + v[3].y*v[3].y), 0.f);
    sb[1][line][padi(j + 448)] = make_float2(sqrtf(v[7].x*v[7].x + v[7].y*v[7].y), 0.f);
    __syncthreads();
    // inverse FFT over l
    load_stage(&sb[1][line][0], v, j);
    fft8<1>(v);
    store_stage<1>(&sb[0][line][0], v, j);
    __syncthreads();
    load_stage(&sb[0][line][0], v, j);
    twiddle<1, 8>(v, j); fft8<1>(v);
    store_stage<8>(&sb[1][line][0], v, j);
    __syncthreads();
    load_stage(&sb[1][line][0], v, j);
    twiddle<1, 64>(v, j); fft8<1>(v);
    int kr = kcb + line;
    if (kr <= 256) {
        float2* o = g_A + (size_t)(b * 257 + kr) * 512;
        o[j] = v[0]; o[j + 64] = v[4]; o[j + 128] = v[2]; o[j + 192] = v[6];
        o[j + 256] = v[1]; o[j + 320] = v[5]; o[j + 384] = v[3]; o[j + 448] = v[7];
    }
}

// ---- pass 4: packed inverse FFT over k (2 h-columns per FFT, Hermitian) ----
// pseudo centrosymmetric -> only h=0..263 needed (h>256 reconstructed by fold)
__global__ __launch_bounds__(256) void k_fft_cols_inv() {
    __shared__ float2 sb[2][4][LSTR];
    int bid = blockIdx.x, b = bid / 33, g = bid % 33, h0 = g << 3;
    int tid = threadIdx.x, line = tid >> 6, j = tid & 63;
    // build s[u][k] = A[k][h0+2u] + i*A[k][h0+2u+1]; k>256 via conj symmetry
#pragma unroll
    for (int it = 0; it < 8; ++it) {
        int idx = it * 256 + tid, u = idx & 3, kk = idx >> 2;
        float2 sv;
        if (kk <= 256) {
            const float4 q4 = *reinterpret_cast<const float4*>(
                g_A + (size_t)(b * 257 + kk) * 512 + h0 + 2 * u);
            sv = make_float2(q4.x - q4.w, q4.y + q4.z);
        } else {
            int k2 = 512 - kk;
            const float4 q4 = *reinterpret_cast<const float4*>(
                g_A + (size_t)(b * 257 + k2) * 512 + h0 + 2 * u);
            sv = make_float2(q4.x + q4.w, q4.z - q4.y);
        }
        sb[0][u][padi(kk)] = sv;
    }
    __syncthreads();
    float2 v[8];
    load_stage(&sb[0][line][0], v, j);
    fft8<1>(v);
    store_stage<1>(&sb[1][line][0], v, j);
    __syncthreads();
    load_stage(&sb[1][line][0], v, j);
    twiddle<1, 8>(v, j); fft8<1>(v);
    store_stage<8>(&sb[0][line][0], v, j);
    __syncthreads();
    load_stage(&sb[0][line][0], v, j);
    twiddle<1, 64>(v, j); fft8<1>(v);
    float* o1 = g_Pb + (size_t)(b * 264 + h0 + 2 * line) * 512;
    float* o2 = o1 + 512;
    o1[j] = v[0].x;       o2[j] = v[0].y;
    o1[j + 64] = v[4].x;  o2[j + 64] = v[4].y;
    o1[j + 128] = v[2].x; o2[j + 128] = v[2].y;
    o1[j + 192] = v[6].x; o2[j + 192] = v[6].y;
    o1[j + 256] = v[1].x; o2[j + 256] = v[1].y;
    o1[j + 320] = v[5].x; o2[j + 320] = v[5].y;
    o1[j + 384] = v[3].x; o2[j + 384] = v[3].y;
    o1[j + 448] = v[7].x; o2[j + 448] = v[7].y;
}

// ---- transpose: [b][h][w] -> [h][w][b]; fold = 2x by centrosymmetry --------
__global__ __launch_bounds__(256) void k_transpose_fold() {
    int bid = blockIdx.x, tid = threadIdx.x;
    const float sc = 1.f / 262144.f;
    if (bid >= 514) {                         // g_c256 fill, h mirrored for h>256
        int hh = (bid - 514) * 256 + tid;
        int src = (hh <= 256) ? hh : 512 - hh;
#pragma unroll
        for (int b = 0; b < 16; ++b)
            g_c256[hh * 16 + b] = g_Pb[((size_t)(b * 264 + src)) * 512 + 256] * sc;
        return;
    }
    __shared__ float tile[256][17];
    int h = bid >> 1, w0 = (bid & 1) << 8;
    int w = w0 + tid;
    float wgt = ((h != 0) && (h != 256)) ? 2.f * sc : sc;   // fold weight
    if (w == 0) wgt *= 0.5f;                                // w=0 self-pairs in contract
#pragma unroll
    for (int b = 0; b < 16; ++b)
        tile[tid][b] = g_Pb[(size_t)(b * 264 + h) * 512 + w] * wgt;
    __syncthreads();
    size_t base = ((size_t)h * 512 + w0) * 16;
    for (int jj = tid; jj < 4096; jj += 256)
        g_Pf[base + jj] = tile[jj >> 4][jj & 15];
}

// ---- mask evaluator: lp0*s(x,0)+lp1*s(x,1)+lp2*s(x,2), rational closed form -
struct MaskC { float Ac, Bc, Cc, s0, l1, l2; };
__device__ __forceinline__ float mask_eval(float x, const MaskC& C) {
    float u = x * x;
    float num = fmaf(fmaf(C.Ac, u, C.Bc), u, C.Cc);
    float den = x * (x - 1.f) * (x + 1.f) * (x - 2.f) * (x + 2.f);
    int ki = __float2int_rn(x);
    float r = x - (float)ki;
    float sv = __sinf(PI_F * r);
    sv = (ki & 1) ? -sv : sv;
    float m = __fdividef(sv * num, PI_F * den);
    if (den == 0.f) {
        float ax = fabsf(x);
        m = (ax == 0.f) ? C.s0 : ((ax == 1.f) ? C.l1 : C.l2);
    }
    return m;
}

// ---- fused mask+contraction: 4 base thetas -> 8 effective via w-mirror ------
// grid (23, 17): spl 0..15 = 16 h-rows each (h=0..255, w'=0..255 paired with 512-w');
// spl 16 = tail: row h=256 (paired) + exact column w=256 from g_c256.
__global__ __launch_bounds__(256) void k_contract(const float* __restrict__ lp) {
    const int grp = blockIdx.x, spl = blockIdx.y, tid = threadIdx.x;
    const float lp0 = __ldg(lp), lp1 = __ldg(lp + 1), lp2 = __ldg(lp + 2);
    MaskC C;
    C.Ac = 2.f * (lp0 - lp1 + lp2);
    C.Bc = 2.f * (-5.f * lp0 + 4.f * lp1 - lp2);
    C.Cc = 8.f * lp0;
    C.s0 = 2.f * lp0; C.l1 = lp1; C.l2 = lp2;

    float ct[4], st_[4];
#pragma unroll
    for (int q = 0; q < 4; ++q) {
        float th = (float)((double)(grp * 4 + q) * 0.017453292519943295);
        ct[q] = cosf(th);
        st_[q] = sinf(th);
    }

    float accp[64], accm[64];
#pragma unroll
    for (int i = 0; i < 64; ++i) { accp[i] = 0.f; accm[i] = 0.f; }

    if (spl < 16) {
        const int h0 = spl * 16;
#pragma unroll 1
        for (int it = 0; it < 16; ++it) {
            int idx = it * 256 + tid;
            int hi = idx >> 8, wp = idx & 255;
            float mf = (float)(h0 + hi);
            float nf = (float)wp;
            int wB = (512 - wp) & 511;

            const float4* pa4 = reinterpret_cast<const float4*>(
                g_Pf + (((size_t)(h0 + hi) * 512 + wp) << 4));
            const float4* pb4 = reinterpret_cast<const float4*>(
                g_Pf + (((size_t)(h0 + hi) * 512 + wB) << 4));
            float4 a0 = pa4[0], a1 = pa4[1], a2 = pa4[2], a3 = pa4[3];
            float4 b0 = pb4[0], b1 = pb4[1], b2 = pb4[2], b3 = pb4[3];
            float pA[16] = {a0.x,a0.y,a0.z,a0.w, a1.x,a1.y,a1.z,a1.w,
                            a2.x,a2.y,a2.z,a2.w, a3.x,a3.y,a3.z,a3.w};
            float pB[16] = {b0.x,b0.y,b0.z,b0.w, b1.x,b1.y,b1.z,b1.w,
                            b2.x,b2.y,b2.z,b2.w, b3.x,b3.y,b3.z,b3.w};

            float Mp[4], Mm[4];
#pragma unroll
            for (int q = 0; q < 4; ++q) {
                Mp[q] = mask_eval(fmaf(mf, ct[q],  nf * st_[q]), C);
                Mm[q] = mask_eval(fmaf(mf, ct[q], -nf * st_[q]), C);
            }
#pragma unroll
            for (int q = 0; q < 4; ++q)
#pragma unroll
                for (int b = 0; b < 16; ++b) {
                    accp[q * 16 + b] = fmaf(Mp[q], pA[b], fmaf(Mm[q], pB[b], accp[q * 16 + b]));
                    accm[q * 16 + b] = fmaf(Mm[q], pA[b], fmaf(Mp[q], pB[b], accm[q * 16 + b]));
                }
        }
    } else {
        // (a) row h=256, paired over w'=0..255
        {
            int wp = tid;
            float mf = -256.f, nf = (float)wp;
            int wB = (512 - wp) & 511;
            const float4* pa4 = reinterpret_cast<const float4*>(
                g_Pf + (((size_t)256 * 512 + wp) << 4));
            const float4* pb4 = reinterpret_cast<const float4*>(
                g_Pf + (((size_t)256 * 512 + wB) << 4));
            float4 a0 = pa4[0], a1 = pa4[1], a2 = pa4[2], a3 = pa4[3];
            float4 b0 = pb4[0], b1 = pb4[1], b2 = pb4[2], b3 = pb4[3];
            float pA[16] = {a0.x,a0.y,a0.z,a0.w, a1.x,a1.y,a1.z,a1.w,
                            a2.x,a2.y,a2.z,a2.w, a3.x,a3.y,a3.z,a3.w};
            float pB[16] = {b0.x,b0.y,b0.z,b0.w, b1.x,b1.y,b1.z,b1.w,
                            b2.x,b2.y,b2.z,b2.w, b3.x,b3.y,b3.z,b3.w};
#pragma unroll
            for (int q = 0; q < 4; ++q) {
                float Mp = mask_eval(fmaf(mf, ct[q],  nf * st_[q]), C);
                float Mm = mask_eval(fmaf(mf, ct[q], -nf * st_[q]), C);
#pragma unroll
                for (int b = 0; b < 16; ++b) {
                    accp[q * 16 + b] = fmaf(Mp, pA[b], fmaf(Mm, pB[b], accp[q * 16 + b]));
                    accm[q * 16 + b] = fmaf(Mm, pA[b], fmaf(Mp, pB[b], accm[q * 16 + b]));
                }
            }
        }
        // (b) column w=256, all h=0..511, exact (unfolded, unpaired)
#pragma unroll 1
        for (int it = 0; it < 2; ++it) {
            int h = it * 256 + tid;
            float mf = (float)(h - ((h >= 256) ? 512 : 0));
            float nf = -256.f;
            const float4* pc4 = reinterpret_cast<const float4*>(g_c256 + h * 16);
            float4 c0 = pc4[0], c1 = pc4[1], c2 = pc4[2], c3 = pc4[3];
            float P[16] = {c0.x,c0.y,c0.z,c0.w, c1.x,c1.y,c1.z,c1.w,
                           c2.x,c2.y,c2.z,c2.w, c3.x,c3.y,c3.z,c3.w};
#pragma unroll
            for (int q = 0; q < 4; ++q) {
                float Mp = mask_eval(fmaf( mf, ct[q], nf * st_[q]), C);   // theta t
                float Mm = mask_eval(fmaf(-mf, ct[q], nf * st_[q]), C);   // theta 180-t
#pragma unroll
                for (int b = 0; b < 16; ++b) {
                    accp[q * 16 + b] = fmaf(Mp, P[b], accp[q * 16 + b]);
                    accm[q * 16 + b] = fmaf(Mm, P[b], accm[q * 16 + b]);
                }
            }
        }
    }

    // deterministic reduction: warp shuffles then smem
#pragma unroll
    for (int i = 0; i < 64; ++i) {
#pragma unroll
        for (int off = 16; off > 0; off >>= 1) {
            accp[i] += __shfl_down_sync(0xffffffffu, accp[i], off);
            accm[i] += __shfl_down_sync(0xffffffffu, accm[i], off);
        }
    }
    __shared__ float red[8][128];
    int wid = tid >> 5, lid = tid & 31;
    if (lid == 0) {
#pragma unroll
        for (int i = 0; i < 64; ++i) {
            red[wid][i] = accp[i];
            red[wid][64 + i] = accm[i];
        }
    }
    __syncthreads();
    if (tid < 128) {
        float s = 0.f;
#pragma unroll
        for (int w8 = 0; w8 < 8; ++w8) s += red[w8][tid];
        g_part[((size_t)grp * 17 + spl) * 128 + tid] = s;
    }
}

// ---- final reduction: map (grp,q,sign) slots -> t; fold einsum 1/(H*W) -----
__global__ __launch_bounds__(256) void k_reduce(float* __restrict__ out) {
    int i = blockIdx.x * 256 + threadIdx.x;
    if (i >= 2880) return;
    int t = i % 180, b = i / 180;
    int bt, sign;
    if (t <= 90) { bt = t; sign = 0; }
    else         { bt = 180 - t; sign = 1; }
    int grp = bt >> 2, q = bt & 3;
    int off = sign * 64 + q * 16 + b;
    float s = 0.f;
#pragma unroll
    for (int spl = 0; spl < 17; ++spl)
        s += g_part[((size_t)grp * 17 + spl) * 128 + off];
    out[b * 180 + t] = s * (1.f / 262144.f);
}

// ---------------------------------------------------------------------------
extern "C" void kernel_launch(void* const* d_in, const int* in_sizes, int n_in,
                              void* d_out, int out_size) {
    const float* batch = (const float*)d_in[0];   // [16,256,256]
    const float* lp    = (const float*)d_in[1];   // [3]
    float* out         = (float*)d_out;           // [16,180]
    (void)in_sizes; (void)n_in; (void)out_size;

    k_fft_rows_fwd<<<1024, 256>>>(batch);
    k_fft_cols_absinv<<<1040, 256>>>();
    k_fft_cols_inv<<<528, 256>>>();
    k_transpose_fold<<<516, 256>>>();
    k_contract<<<dim3(23, 17), 256>>>(lp);
    k_reduce<<<12, 256>>>(out);
}